// round 13
// baseline (speedup 1.0000x reference)
#include <cuda_runtime.h>
#include <cuda_bf16.h>
#include <math.h>

// Problem constants
#define Bq      4
#define QLEN    512
#define KLEN    4096
#define DMODEL  1024
#define NH      8
#define DHEAD   128

// ---------------------------------------------------------------------------
// Scratch (device globals — allocation-free rule)
// ---------------------------------------------------------------------------
__device__ float g_q [(size_t)Bq * QLEN * NH * DHEAD];          // 8 MB
__device__ float g_kv[(size_t)Bq * KLEN * NH * 2 * DHEAD];      // 128 MB
__device__ float g_o [(size_t)Bq * QLEN * NH * DHEAD];          // 8 MB

// ---------------------------------------------------------------------------
// SGEMM: C[M,N] = A[M,K] * B[K,N] (+ bias), all row-major.
// 128x128 tile, BK=8, 256 threads, 8x8 per-thread microtile,
// register prefetch + double-buffered smem, one __syncthreads per K-step.
// Requires M%128==0, N%128==0, K%8==0 (true for all our shapes).
// ---------------------------------------------------------------------------
__global__ __launch_bounds__(256, 2) void sgemm128(
    const float* __restrict__ A, const float* __restrict__ B,
    const float* __restrict__ bias, float* __restrict__ C,
    int M, int N, int K)
{
    __shared__ float As[2][8][128];   // stored transposed: As[k][m]
    __shared__ float Bs[2][8][128];

    const int tid = threadIdx.x;
    const int tx  = tid & 15;
    const int ty  = tid >> 4;
    const int m0  = blockIdx.y * 128;
    const int n0  = blockIdx.x * 128;

    // global->smem load mapping
    const int arow = tid >> 1;            // 0..127
    const int acol = (tid & 1) << 2;      // 0 or 4
    const int brow = tid >> 5;            // 0..7
    const int bcol = (tid & 31) << 2;     // 0..124

    const float* Ag = A + (size_t)(m0 + arow) * K + acol;
    const float* Bg = B + (size_t)brow * N + n0 + bcol;

    float4 av = *(const float4*)Ag;
    float4 bv = *(const float4*)Bg;

    float acc[8][8];
#pragma unroll
    for (int i = 0; i < 8; i++)
#pragma unroll
        for (int j = 0; j < 8; j++) acc[i][j] = 0.f;

    const int nk = K >> 3;
    int buf = 0;
    for (int kt = 0; kt < nk; kt++) {
        // store current tile to smem
        As[buf][acol + 0][arow] = av.x;
        As[buf][acol + 1][arow] = av.y;
        As[buf][acol + 2][arow] = av.z;
        As[buf][acol + 3][arow] = av.w;
        *(float4*)&Bs[buf][brow][bcol] = bv;
        __syncthreads();

        // prefetch next tile to registers (overlaps with compute below)
        if (kt + 1 < nk) {
            av = *(const float4*)(Ag + (size_t)(kt + 1) * 8);
            bv = *(const float4*)(Bg + (size_t)(kt + 1) * 8 * N);
        }

#pragma unroll
        for (int k = 0; k < 8; k++) {
            float a[8], b[8];
            *(float4*)&a[0] = *(const float4*)&As[buf][k][ty * 4];
            *(float4*)&a[4] = *(const float4*)&As[buf][k][ty * 4 + 64];
            *(float4*)&b[0] = *(const float4*)&Bs[buf][k][tx * 4];
            *(float4*)&b[4] = *(const float4*)&Bs[buf][k][tx * 4 + 64];
#pragma unroll
            for (int i = 0; i < 8; i++)
#pragma unroll
                for (int j = 0; j < 8; j++)
                    acc[i][j] += a[i] * b[j];
        }
        buf ^= 1;
    }

#pragma unroll
    for (int ii = 0; ii < 2; ii++)
#pragma unroll
        for (int i = 0; i < 4; i++) {
            const int row = m0 + ty * 4 + i + ii * 64;
#pragma unroll
            for (int jj = 0; jj < 2; jj++) {
                const int col = n0 + tx * 4 + jj * 64;
                float4 v;
                v.x = acc[ii * 4 + i][jj * 4 + 0];
                v.y = acc[ii * 4 + i][jj * 4 + 1];
                v.z = acc[ii * 4 + i][jj * 4 + 2];
                v.w = acc[ii * 4 + i][jj * 4 + 3];
                if (bias) {
                    float4 bb = *(const float4*)&bias[col];
                    v.x += bb.x; v.y += bb.y; v.z += bb.z; v.w += bb.w;
                }
                *(float4*)&C[(size_t)row * N + col] = v;
            }
        }
}

// ---------------------------------------------------------------------------
// Flash attention, fp32, 64 queries x 64 keys per tile, 256 threads.
// Q,K stored transposed (contraction-major) + XOR swizzle -> conflict-free
// LDS.128 operand loads in the S-GEMM.
// ---------------------------------------------------------------------------
#define QT_STRIDE 68
#define ATT_SMEM_FLOATS (128 * QT_STRIDE * 2 + 64 * 128 + 64 * QT_STRIDE)
#define ATT_SMEM_BYTES  (ATT_SMEM_FLOATS * 4)

__device__ __forceinline__ void fma44(float4& a, float p, const float4& v) {
    a.x += p * v.x; a.y += p * v.y; a.z += p * v.z; a.w += p * v.w;
}
__device__ __forceinline__ void scale4(float4& a, float c) {
    a.x *= c; a.y *= c; a.z *= c; a.w *= c;
}

__device__ __forceinline__ void softmax_row(
    float4 s, float scale, float& m, float& l,
    float4& oa, float4& ob, float* Ps, int rowoff, int tx)
{
    float a0 = s.x * scale, a1 = s.y * scale, a2 = s.z * scale, a3 = s.w * scale;
    float rm = fmaxf(fmaxf(a0, a1), fmaxf(a2, a3));
#pragma unroll
    for (int msk = 1; msk < 16; msk <<= 1)
        rm = fmaxf(rm, __shfl_xor_sync(0xffffffffu, rm, msk));
    const float mn   = fmaxf(m, rm);
    const float corr = __expf(m - mn);
    m = mn;
    float p0 = __expf(a0 - mn), p1 = __expf(a1 - mn);
    float p2 = __expf(a2 - mn), p3 = __expf(a3 - mn);
    float rsum = p0 + p1 + p2 + p3;
#pragma unroll
    for (int msk = 1; msk < 16; msk <<= 1)
        rsum += __shfl_xor_sync(0xffffffffu, rsum, msk);
    l = l * corr + rsum;
    scale4(oa, corr);
    scale4(ob, corr);
    *(float4*)&Ps[rowoff + tx * 4] = make_float4(p0, p1, p2, p3);
}

__global__ __launch_bounds__(256, 1) void attn_kernel(
    const float* __restrict__ Qm, const float* __restrict__ KVm,
    float* __restrict__ Om)
{
    extern __shared__ float sm[];
    float* Qt = sm;                        // [128][68] kk-major, swizzled
    float* Kt = Qt + 128 * QT_STRIDE;      // [128][68]
    float* Vs = Kt + 128 * QT_STRIDE;      // [64][128] row-major
    float* Ps = Vs + 64 * 128;             // [64][68]

    const int tid = threadIdx.x;
    const int tx  = tid & 15;
    const int ty  = tid >> 4;
    const int q0  = blockIdx.x * 64;
    const int h   = blockIdx.y;
    const int b   = blockIdx.z;

    const float scale = 0.088388347648318447f;  // 1/sqrt(128)

    // ---- load Q tile (transposed + XOR swizzle) ----
    const float* Qbase = Qm + ((size_t)(b * QLEN + q0) * NH + h) * DHEAD;
#pragma unroll
    for (int it = 0; it < 8; it++) {
        const int idx = tid + it * 256;        // 0..2047
        const int r   = idx >> 5;              // query row 0..63
        const int c4  = (idx & 31) << 2;       // dh col, step 4
        float4 v = *(const float4*)(Qbase + (size_t)r * (NH * DHEAD) + c4);
        const int f  = c4 & 28;
        const int rs = r ^ f;
        Qt[(c4 + 0) * QT_STRIDE + rs] = v.x;
        Qt[(c4 + 1) * QT_STRIDE + rs] = v.y;
        Qt[(c4 + 2) * QT_STRIDE + rs] = v.z;
        Qt[(c4 + 3) * QT_STRIDE + rs] = v.w;
    }

    float  m_i[4], l_i[4];
    float4 oA[4], oB[4];
#pragma unroll
    for (int i = 0; i < 4; i++) {
        m_i[i] = -1e30f; l_i[i] = 0.f;
        oA[i] = make_float4(0.f, 0.f, 0.f, 0.f);
        oB[i] = make_float4(0.f, 0.f, 0.f, 0.f);
    }

    for (int kt = 0; kt < KLEN / 64; kt++) {
        __syncthreads();   // prior tile's smem reads done (also fences Q stores on kt==0)

        // ---- load K (transposed+swizzled) and V (row-major) tiles ----
        const int k0 = kt * 64;
        const float* Kbase = KVm + ((size_t)(b * KLEN + k0) * NH + h) * (2 * DHEAD);
#pragma unroll
        for (int it = 0; it < 8; it++) {
            const int idx = tid + it * 256;
            const int r   = idx >> 5;
            const int c4  = (idx & 31) << 2;
            const float* rowp = Kbase + (size_t)r * (NH * 2 * DHEAD);
            float4 kv4 = *(const float4*)(rowp + c4);
            const int f  = c4 & 28;
            const int rs = r ^ f;
            Kt[(c4 + 0) * QT_STRIDE + rs] = kv4.x;
            Kt[(c4 + 1) * QT_STRIDE + rs] = kv4.y;
            Kt[(c4 + 2) * QT_STRIDE + rs] = kv4.z;
            Kt[(c4 + 3) * QT_STRIDE + rs] = kv4.w;
            float4 v4 = *(const float4*)(rowp + DHEAD + c4);
            *(float4*)&Vs[r * 128 + c4] = v4;
        }
        __syncthreads();

        // ---- S = Q K^T  (rows ty*4.., cols tx*4..) ----
        float4 s0 = make_float4(0.f, 0.f, 0.f, 0.f);
        float4 s1 = s0, s2 = s0, s3 = s0;
#pragma unroll 8
        for (int kk = 0; kk < 128; kk++) {
            const int f = kk & 28;
            float4 a  = *(const float4*)&Qt[kk * QT_STRIDE + ((ty * 4) ^ f)];
            float4 bq = *(const float4*)&Kt[kk * QT_STRIDE + ((tx * 4) ^ f)];
            s0.x += a.x * bq.x; s0.y += a.x * bq.y; s0.z += a.x * bq.z; s0.w += a.x * bq.w;
            s1.x += a.y * bq.x; s1.y += a.y * bq.y; s1.z += a.y * bq.z; s1.w += a.y * bq.w;
            s2.x += a.z * bq.x; s2.y += a.z * bq.y; s2.z += a.z * bq.z; s2.w += a.z * bq.w;
            s3.x += a.w * bq.x; s3.y += a.w * bq.y; s3.z += a.w * bq.z; s3.w += a.w * bq.w;
        }

        // ---- online softmax update (per row), write P tile ----
        softmax_row(s0, scale, m_i[0], l_i[0], oA[0], oB[0], Ps, (ty * 4 + 0) * QT_STRIDE, tx);
        softmax_row(s1, scale, m_i[1], l_i[1], oA[1], oB[1], Ps, (ty * 4 + 1) * QT_STRIDE, tx);
        softmax_row(s2, scale, m_i[2], l_i[2], oA[2], oB[2], Ps, (ty * 4 + 2) * QT_STRIDE, tx);
        softmax_row(s3, scale, m_i[3], l_i[3], oA[3], oB[3], Ps, (ty * 4 + 3) * QT_STRIDE, tx);
        __syncthreads();

        // ---- O += P * V  (rows ty*4.., dh cols tx*8..) ----
#pragma unroll 2
        for (int j4 = 0; j4 < 16; j4++) {
            const int pb = j4 * 4;
            float4 pr0 = *(const float4*)&Ps[(ty * 4 + 0) * QT_STRIDE + pb];
            float4 pr1 = *(const float4*)&Ps[(ty * 4 + 1) * QT_STRIDE + pb];
            float4 pr2 = *(const float4*)&Ps[(ty * 4 + 2) * QT_STRIDE + pb];
            float4 pr3 = *(const float4*)&Ps[(ty * 4 + 3) * QT_STRIDE + pb];
#pragma unroll
            for (int jj = 0; jj < 4; jj++) {
                const float p0 = (jj == 0) ? pr0.x : (jj == 1) ? pr0.y : (jj == 2) ? pr0.z : pr0.w;
                const float p1 = (jj == 0) ? pr1.x : (jj == 1) ? pr1.y : (jj == 2) ? pr1.z : pr1.w;
                const float p2 = (jj == 0) ? pr2.x : (jj == 1) ? pr2.y : (jj == 2) ? pr2.z : pr2.w;
                const float p3 = (jj == 0) ? pr3.x : (jj == 1) ? pr3.y : (jj == 2) ? pr3.z : pr3.w;
                float4 v0 = *(const float4*)&Vs[(pb + jj) * 128 + tx * 8];
                float4 v1 = *(const float4*)&Vs[(pb + jj) * 128 + tx * 8 + 4];
                fma44(oA[0], p0, v0); fma44(oB[0], p0, v1);
                fma44(oA[1], p1, v0); fma44(oB[1], p1, v1);
                fma44(oA[2], p2, v0); fma44(oB[2], p2, v1);
                fma44(oA[3], p3, v0); fma44(oB[3], p3, v1);
            }
        }
    }

    // ---- epilogue: normalize and store ----
    float* Obase = Om + ((size_t)(b * QLEN + q0) * NH + h) * DHEAD;
#pragma unroll
    for (int i = 0; i < 4; i++) {
        const int r = ty * 4 + i;
        const float inv = 1.f / l_i[i];
        float4 v0 = oA[i], v1 = oB[i];
        scale4(v0, inv);
        scale4(v1, inv);
        *(float4*)&Obase[(size_t)r * (NH * DHEAD) + tx * 8]     = v0;
        *(float4*)&Obase[(size_t)r * (NH * DHEAD) + tx * 8 + 4] = v1;
    }
}

// ---------------------------------------------------------------------------
// Launch
// ---------------------------------------------------------------------------
extern "C" void kernel_launch(void* const* d_in, const int* in_sizes, int n_in,
                              void* d_out, int out_size)
{
    (void)in_sizes; (void)n_in; (void)out_size;

    const float* inputs_q  = (const float*)d_in[0];
    const float* inputs_kv = (const float*)d_in[1];
    const float* Wq        = (const float*)d_in[2];
    const float* Wkv       = (const float*)d_in[3];
    const float* Wproj     = (const float*)d_in[4];
    const float* bproj     = (const float*)d_in[5];
    float* out = (float*)d_out;

    // One-time setup (first call is the uncaptured correctness run).
    static float* qp  = nullptr;
    static float* kvp = nullptr;
    static float* op  = nullptr;
    static bool inited = false;
    if (!inited) {
        void* p;
        cudaGetSymbolAddress(&p, g_q);  qp  = (float*)p;
        cudaGetSymbolAddress(&p, g_kv); kvp = (float*)p;
        cudaGetSymbolAddress(&p, g_o);  op  = (float*)p;
        cudaFuncSetAttribute(attn_kernel, cudaFuncAttributeMaxDynamicSharedMemorySize,
                             ATT_SMEM_BYTES);
        inited = true;
    }

    const dim3 blk(256);

    // 1) q = inputs_q @ Wq          [2048,1024] x [1024,1024]
    sgemm128<<<dim3(DMODEL / 128, (Bq * QLEN) / 128), blk>>>(
        inputs_q, Wq, nullptr, qp, Bq * QLEN, NH * DHEAD, DMODEL);

    // 2) kv = inputs_kv @ Wkv       [16384,1024] x [1024,2048]
    sgemm128<<<dim3((NH * 2 * DHEAD) / 128, (Bq * KLEN) / 128), blk>>>(
        inputs_kv, Wkv, nullptr, kvp, Bq * KLEN, NH * 2 * DHEAD, DMODEL);

    // 3) flash attention -> o
    attn_kernel<<<dim3(QLEN / 64, NH, Bq), blk, ATT_SMEM_BYTES>>>(qp, kvp, op);

    // 4) out = o @ Wproj + b        [2048,1024] x [1024,1024]
    sgemm128<<<dim3(DMODEL / 128, (Bq * QLEN) / 128), blk>>>(
        op, Wproj, bproj, out, Bq * QLEN, DMODEL, NH * DHEAD);
}

// round 14
// speedup vs baseline: 1.2704x; 1.2704x over previous
#include <cuda_runtime.h>
#include <cuda_bf16.h>
#include <math.h>

// Problem constants
#define Bq      4
#define QLEN    512
#define KLEN    4096
#define DMODEL  1024
#define NH      8
#define DHEAD   128

// ---------------------------------------------------------------------------
// Scratch (device globals — allocation-free rule)
// ---------------------------------------------------------------------------
__device__ float g_q [(size_t)Bq * QLEN * NH * DHEAD];          // 8 MB
__device__ float g_kv[(size_t)Bq * KLEN * NH * 2 * DHEAD];      // 128 MB
__device__ float g_o [(size_t)Bq * QLEN * NH * DHEAD];          // 8 MB

// ===========================================================================
// bf16x3 tensor-core GEMM: C[M,N] = A[M,K] * B[K,N] (+bias), fp32 in/out.
// Split each fp32 into bf16 hi+lo; accumulate AhBh + AhBl + AlBh in fp32 via
// mma.sync.m16n8k16 -> ~16-bit effective mantissa (rel err ~1e-5).
// Block tile 128x128, BK=32, 256 threads (8 warps as 2(m) x 4(n), warp tile
// 64x32), double-buffered smem, register gmem prefetch.
// Requires M%128==0, N%128==0, K%32==0.
// ===========================================================================
#define A_PITCH 40    // bf16 elems per A smem row (conflict-free frag loads)
#define B_PITCH 136   // bf16 elems per B smem row
#define GEMM_A_ELTS (128 * A_PITCH)          // 5120
#define GEMM_B_ELTS (32 * B_PITCH)           // 4352
#define GEMM_BUF_ELTS (2 * GEMM_A_ELTS + 2 * GEMM_B_ELTS)   // 18944
#define GEMM_SMEM_BYTES (2 * GEMM_BUF_ELTS * 2)             // 75776

__device__ __forceinline__ unsigned pk16(__nv_bfloat16 lo, __nv_bfloat16 hi) {
    return (unsigned)__bfloat16_as_ushort(lo) |
           ((unsigned)__bfloat16_as_ushort(hi) << 16);
}
__device__ __forceinline__ void split_bf16(float x, __nv_bfloat16& h, __nv_bfloat16& l) {
    h = __float2bfloat16(x);
    l = __float2bfloat16(x - __bfloat162float(h));
}
__device__ __forceinline__ void mma16816(float* c, const unsigned* a, const unsigned* b) {
    asm volatile(
        "mma.sync.aligned.m16n8k16.row.col.f32.bf16.bf16.f32 "
        "{%0,%1,%2,%3}, {%4,%5,%6,%7}, {%8,%9}, {%0,%1,%2,%3};\n"
        : "+f"(c[0]), "+f"(c[1]), "+f"(c[2]), "+f"(c[3])
        : "r"(a[0]), "r"(a[1]), "r"(a[2]), "r"(a[3]), "r"(b[0]), "r"(b[1]));
}

__global__ __launch_bounds__(256, 1) void gemm_bf16x3(
    const float* __restrict__ A, const float* __restrict__ B,
    const float* __restrict__ bias, float* __restrict__ C,
    int M, int N, int K)
{
    extern __shared__ __nv_bfloat16 smg[];

    const int tid  = threadIdx.x;
    const int lane = tid & 31;
    const int wid  = tid >> 5;
    const int wm   = wid & 1;      // 0..1 : warp row (64 rows each)
    const int wn   = wid >> 1;     // 0..3 : warp col (32 cols each)
    const int m0   = blockIdx.y * 128;
    const int n0   = blockIdx.x * 128;

    // gmem load mapping (per thread: 4 float4 of A, 4 float4 of B per BK step)
    const int a_r = tid >> 3;              // 0..31 (row group, +it*32)
    const int a_c = (tid & 7) * 4;         // k col 0..28
    const int b_r = tid >> 5;              // 0..7  (k row, +it*8)
    const int b_c = (tid & 31) * 4;        // n col 0..124

    const float* Ag = A + (size_t)(m0 + a_r) * K + a_c;
    const float* Bg = B + (size_t)b_r * N + n0 + b_c;

    float4 apre[4], bpre[4];
#pragma unroll
    for (int it = 0; it < 4; it++) {
        apre[it] = *(const float4*)(Ag + (size_t)(it * 32) * K);
        bpre[it] = *(const float4*)(Bg + (size_t)(it * 8) * N);
    }

    float acc[4][4][4];
#pragma unroll
    for (int mt = 0; mt < 4; mt++)
#pragma unroll
        for (int nt = 0; nt < 4; nt++)
#pragma unroll
            for (int i = 0; i < 4; i++) acc[mt][nt][i] = 0.f;

    const int nk = K / 32;
    int buf = 0;
    for (int kt = 0; kt < nk; kt++) {
        __nv_bfloat16* Ah = smg + buf * GEMM_BUF_ELTS;
        __nv_bfloat16* Al = Ah + GEMM_A_ELTS;
        __nv_bfloat16* Bh = Ah + 2 * GEMM_A_ELTS;
        __nv_bfloat16* Bl = Bh + GEMM_B_ELTS;

        // ---- split + store current tiles to smem ----
#pragma unroll
        for (int it = 0; it < 4; it++) {
            {
                float4 v = apre[it];
                __nv_bfloat16 h0, h1, h2, h3, l0, l1, l2, l3;
                split_bf16(v.x, h0, l0); split_bf16(v.y, h1, l1);
                split_bf16(v.z, h2, l2); split_bf16(v.w, h3, l3);
                const int off = (a_r + it * 32) * A_PITCH + a_c;
                uint2 uh; uh.x = pk16(h0, h1); uh.y = pk16(h2, h3);
                uint2 ul; ul.x = pk16(l0, l1); ul.y = pk16(l2, l3);
                *(uint2*)&Ah[off] = uh;
                *(uint2*)&Al[off] = ul;
            }
            {
                float4 v = bpre[it];
                __nv_bfloat16 h0, h1, h2, h3, l0, l1, l2, l3;
                split_bf16(v.x, h0, l0); split_bf16(v.y, h1, l1);
                split_bf16(v.z, h2, l2); split_bf16(v.w, h3, l3);
                const int off = (b_r + it * 8) * B_PITCH + b_c;
                uint2 uh; uh.x = pk16(h0, h1); uh.y = pk16(h2, h3);
                uint2 ul; ul.x = pk16(l0, l1); ul.y = pk16(l2, l3);
                *(uint2*)&Bh[off] = uh;
                *(uint2*)&Bl[off] = ul;
            }
        }
        __syncthreads();

        // ---- prefetch next tiles to registers ----
        if (kt + 1 < nk) {
            const int knext = (kt + 1) * 32;
#pragma unroll
            for (int it = 0; it < 4; it++) {
                apre[it] = *(const float4*)(Ag + (size_t)(it * 32) * K + knext);
                bpre[it] = *(const float4*)(Bg + (size_t)(knext + it * 8) * N);
            }
        }

        // ---- compute: two k16 halves ----
#pragma unroll
        for (int h16 = 0; h16 < 2; h16++) {
            const int kb = h16 * 16;
            unsigned ah[4][4], al[4][4];
#pragma unroll
            for (int mt = 0; mt < 4; mt++) {
                const int r0 = wm * 64 + mt * 16 + (lane >> 2);
                const int cc = kb + (lane & 3) * 2;
                ah[mt][0] = *(const unsigned*)&Ah[r0 * A_PITCH + cc];
                ah[mt][1] = *(const unsigned*)&Ah[(r0 + 8) * A_PITCH + cc];
                ah[mt][2] = *(const unsigned*)&Ah[r0 * A_PITCH + cc + 8];
                ah[mt][3] = *(const unsigned*)&Ah[(r0 + 8) * A_PITCH + cc + 8];
                al[mt][0] = *(const unsigned*)&Al[r0 * A_PITCH + cc];
                al[mt][1] = *(const unsigned*)&Al[(r0 + 8) * A_PITCH + cc];
                al[mt][2] = *(const unsigned*)&Al[r0 * A_PITCH + cc + 8];
                al[mt][3] = *(const unsigned*)&Al[(r0 + 8) * A_PITCH + cc + 8];
            }
            unsigned bh[4][2], bl[4][2];
#pragma unroll
            for (int nt = 0; nt < 4; nt++) {
                const int nc = wn * 32 + nt * 8 + (lane >> 2);
                const int k0 = kb + (lane & 3) * 2;
                bh[nt][0] = pk16(Bh[k0 * B_PITCH + nc],       Bh[(k0 + 1) * B_PITCH + nc]);
                bh[nt][1] = pk16(Bh[(k0 + 8) * B_PITCH + nc], Bh[(k0 + 9) * B_PITCH + nc]);
                bl[nt][0] = pk16(Bl[k0 * B_PITCH + nc],       Bl[(k0 + 1) * B_PITCH + nc]);
                bl[nt][1] = pk16(Bl[(k0 + 8) * B_PITCH + nc], Bl[(k0 + 9) * B_PITCH + nc]);
            }
#pragma unroll
            for (int mt = 0; mt < 4; mt++)
#pragma unroll
                for (int nt = 0; nt < 4; nt++) {
                    mma16816(acc[mt][nt], ah[mt], bh[nt]);
                    mma16816(acc[mt][nt], ah[mt], bl[nt]);
                    mma16816(acc[mt][nt], al[mt], bh[nt]);
                }
        }
        buf ^= 1;
    }

    // ---- epilogue ----
#pragma unroll
    for (int mt = 0; mt < 4; mt++) {
        const int gm = m0 + wm * 64 + mt * 16 + (lane >> 2);
#pragma unroll
        for (int nt = 0; nt < 4; nt++) {
            const int gn = n0 + wn * 32 + nt * 8 + (lane & 3) * 2;
            float2 v0 = make_float2(acc[mt][nt][0], acc[mt][nt][1]);
            float2 v1 = make_float2(acc[mt][nt][2], acc[mt][nt][3]);
            if (bias) {
                float2 bb = *(const float2*)&bias[gn];
                v0.x += bb.x; v0.y += bb.y;
                v1.x += bb.x; v1.y += bb.y;
            }
            *(float2*)&C[(size_t)gm * N + gn]       = v0;
            *(float2*)&C[(size_t)(gm + 8) * N + gn] = v1;
        }
    }
}

// ---------------------------------------------------------------------------
// Flash attention, fp32, 64 queries x 64 keys per tile, 256 threads.
// (unchanged from round 12 — next optimization target)
// ---------------------------------------------------------------------------
#define QT_STRIDE 68
#define ATT_SMEM_FLOATS (128 * QT_STRIDE * 2 + 64 * 128 + 64 * QT_STRIDE)
#define ATT_SMEM_BYTES  (ATT_SMEM_FLOATS * 4)

__device__ __forceinline__ void fma44(float4& a, float p, const float4& v) {
    a.x += p * v.x; a.y += p * v.y; a.z += p * v.z; a.w += p * v.w;
}
__device__ __forceinline__ void scale4(float4& a, float c) {
    a.x *= c; a.y *= c; a.z *= c; a.w *= c;
}

__device__ __forceinline__ void softmax_row(
    float4 s, float scale, float& m, float& l,
    float4& oa, float4& ob, float* Ps, int rowoff, int tx)
{
    float a0 = s.x * scale, a1 = s.y * scale, a2 = s.z * scale, a3 = s.w * scale;
    float rm = fmaxf(fmaxf(a0, a1), fmaxf(a2, a3));
#pragma unroll
    for (int msk = 1; msk < 16; msk <<= 1)
        rm = fmaxf(rm, __shfl_xor_sync(0xffffffffu, rm, msk));
    const float mn   = fmaxf(m, rm);
    const float corr = __expf(m - mn);
    m = mn;
    float p0 = __expf(a0 - mn), p1 = __expf(a1 - mn);
    float p2 = __expf(a2 - mn), p3 = __expf(a3 - mn);
    float rsum = p0 + p1 + p2 + p3;
#pragma unroll
    for (int msk = 1; msk < 16; msk <<= 1)
        rsum += __shfl_xor_sync(0xffffffffu, rsum, msk);
    l = l * corr + rsum;
    scale4(oa, corr);
    scale4(ob, corr);
    *(float4*)&Ps[rowoff + tx * 4] = make_float4(p0, p1, p2, p3);
}

__global__ __launch_bounds__(256, 1) void attn_kernel(
    const float* __restrict__ Qm, const float* __restrict__ KVm,
    float* __restrict__ Om)
{
    extern __shared__ float sm[];
    float* Qt = sm;                        // [128][68] kk-major, swizzled
    float* Kt = Qt + 128 * QT_STRIDE;      // [128][68]
    float* Vs = Kt + 128 * QT_STRIDE;      // [64][128] row-major
    float* Ps = Vs + 64 * 128;             // [64][68]

    const int tid = threadIdx.x;
    const int tx  = tid & 15;
    const int ty  = tid >> 4;
    const int q0  = blockIdx.x * 64;
    const int h   = blockIdx.y;
    const int b   = blockIdx.z;

    const float scale = 0.088388347648318447f;  // 1/sqrt(128)

    // ---- load Q tile (transposed + XOR swizzle) ----
    const float* Qbase = Qm + ((size_t)(b * QLEN + q0) * NH + h) * DHEAD;
#pragma unroll
    for (int it = 0; it < 8; it++) {
        const int idx = tid + it * 256;        // 0..2047
        const int r   = idx >> 5;              // query row 0..63
        const int c4  = (idx & 31) << 2;       // dh col, step 4
        float4 v = *(const float4*)(Qbase + (size_t)r * (NH * DHEAD) + c4);
        const int f  = c4 & 28;
        const int rs = r ^ f;
        Qt[(c4 + 0) * QT_STRIDE + rs] = v.x;
        Qt[(c4 + 1) * QT_STRIDE + rs] = v.y;
        Qt[(c4 + 2) * QT_STRIDE + rs] = v.z;
        Qt[(c4 + 3) * QT_STRIDE + rs] = v.w;
    }

    float  m_i[4], l_i[4];
    float4 oA[4], oB[4];
#pragma unroll
    for (int i = 0; i < 4; i++) {
        m_i[i] = -1e30f; l_i[i] = 0.f;
        oA[i] = make_float4(0.f, 0.f, 0.f, 0.f);
        oB[i] = make_float4(0.f, 0.f, 0.f, 0.f);
    }

    for (int kt = 0; kt < KLEN / 64; kt++) {
        __syncthreads();   // prior tile's smem reads done (also fences Q stores on kt==0)

        // ---- load K (transposed+swizzled) and V (row-major) tiles ----
        const int k0 = kt * 64;
        const float* Kbase = KVm + ((size_t)(b * KLEN + k0) * NH + h) * (2 * DHEAD);
#pragma unroll
        for (int it = 0; it < 8; it++) {
            const int idx = tid + it * 256;
            const int r   = idx >> 5;
            const int c4  = (idx & 31) << 2;
            const float* rowp = Kbase + (size_t)r * (NH * 2 * DHEAD);
            float4 kv4 = *(const float4*)(rowp + c4);
            const int f  = c4 & 28;
            const int rs = r ^ f;
            Kt[(c4 + 0) * QT_STRIDE + rs] = kv4.x;
            Kt[(c4 + 1) * QT_STRIDE + rs] = kv4.y;
            Kt[(c4 + 2) * QT_STRIDE + rs] = kv4.z;
            Kt[(c4 + 3) * QT_STRIDE + rs] = kv4.w;
            float4 v4 = *(const float4*)(rowp + DHEAD + c4);
            *(float4*)&Vs[r * 128 + c4] = v4;
        }
        __syncthreads();

        // ---- S = Q K^T  (rows ty*4.., cols tx*4..) ----
        float4 s0 = make_float4(0.f, 0.f, 0.f, 0.f);
        float4 s1 = s0, s2 = s0, s3 = s0;
#pragma unroll 8
        for (int kk = 0; kk < 128; kk++) {
            const int f = kk & 28;
            float4 a  = *(const float4*)&Qt[kk * QT_STRIDE + ((ty * 4) ^ f)];
            float4 bq = *(const float4*)&Kt[kk * QT_STRIDE + ((tx * 4) ^ f)];
            s0.x += a.x * bq.x; s0.y += a.x * bq.y; s0.z += a.x * bq.z; s0.w += a.x * bq.w;
            s1.x += a.y * bq.x; s1.y += a.y * bq.y; s1.z += a.y * bq.z; s1.w += a.y * bq.w;
            s2.x += a.z * bq.x; s2.y += a.z * bq.y; s2.z += a.z * bq.z; s2.w += a.z * bq.w;
            s3.x += a.w * bq.x; s3.y += a.w * bq.y; s3.z += a.w * bq.z; s3.w += a.w * bq.w;
        }

        // ---- online softmax update (per row), write P tile ----
        softmax_row(s0, scale, m_i[0], l_i[0], oA[0], oB[0], Ps, (ty * 4 + 0) * QT_STRIDE, tx);
        softmax_row(s1, scale, m_i[1], l_i[1], oA[1], oB[1], Ps, (ty * 4 + 1) * QT_STRIDE, tx);
        softmax_row(s2, scale, m_i[2], l_i[2], oA[2], oB[2], Ps, (ty * 4 + 2) * QT_STRIDE, tx);
        softmax_row(s3, scale, m_i[3], l_i[3], oA[3], oB[3], Ps, (ty * 4 + 3) * QT_STRIDE, tx);
        __syncthreads();

        // ---- O += P * V  (rows ty*4.., dh cols tx*8..) ----
#pragma unroll 2
        for (int j4 = 0; j4 < 16; j4++) {
            const int pb = j4 * 4;
            float4 pr0 = *(const float4*)&Ps[(ty * 4 + 0) * QT_STRIDE + pb];
            float4 pr1 = *(const float4*)&Ps[(ty * 4 + 1) * QT_STRIDE + pb];
            float4 pr2 = *(const float4*)&Ps[(ty * 4 + 2) * QT_STRIDE + pb];
            float4 pr3 = *(const float4*)&Ps[(ty * 4 + 3) * QT_STRIDE + pb];
#pragma unroll
            for (int jj = 0; jj < 4; jj++) {
                const float p0 = (jj == 0) ? pr0.x : (jj == 1) ? pr0.y : (jj == 2) ? pr0.z : pr0.w;
                const float p1 = (jj == 0) ? pr1.x : (jj == 1) ? pr1.y : (jj == 2) ? pr1.z : pr1.w;
                const float p2 = (jj == 0) ? pr2.x : (jj == 1) ? pr2.y : (jj == 2) ? pr2.z : pr2.w;
                const float p3 = (jj == 0) ? pr3.x : (jj == 1) ? pr3.y : (jj == 2) ? pr3.z : pr3.w;
                float4 v0 = *(const float4*)&Vs[(pb + jj) * 128 + tx * 8];
                float4 v1 = *(const float4*)&Vs[(pb + jj) * 128 + tx * 8 + 4];
                fma44(oA[0], p0, v0); fma44(oB[0], p0, v1);
                fma44(oA[1], p1, v0); fma44(oB[1], p1, v1);
                fma44(oA[2], p2, v0); fma44(oB[2], p2, v1);
                fma44(oA[3], p3, v0); fma44(oB[3], p3, v1);
            }
        }
    }

    // ---- epilogue: normalize and store ----
    float* Obase = Om + ((size_t)(b * QLEN + q0) * NH + h) * DHEAD;
#pragma unroll
    for (int i = 0; i < 4; i++) {
        const int r = ty * 4 + i;
        const float inv = 1.f / l_i[i];
        float4 v0 = oA[i], v1 = oB[i];
        scale4(v0, inv);
        scale4(v1, inv);
        *(float4*)&Obase[(size_t)r * (NH * DHEAD) + tx * 8]     = v0;
        *(float4*)&Obase[(size_t)r * (NH * DHEAD) + tx * 8 + 4] = v1;
    }
}

// ---------------------------------------------------------------------------
// Launch
// ---------------------------------------------------------------------------
extern "C" void kernel_launch(void* const* d_in, const int* in_sizes, int n_in,
                              void* d_out, int out_size)
{
    (void)in_sizes; (void)n_in; (void)out_size;

    const float* inputs_q  = (const float*)d_in[0];
    const float* inputs_kv = (const float*)d_in[1];
    const float* Wq        = (const float*)d_in[2];
    const float* Wkv       = (const float*)d_in[3];
    const float* Wproj     = (const float*)d_in[4];
    const float* bproj     = (const float*)d_in[5];
    float* out = (float*)d_out;

    // One-time setup (first call is the uncaptured correctness run).
    static float* qp  = nullptr;
    static float* kvp = nullptr;
    static float* op  = nullptr;
    static bool inited = false;
    if (!inited) {
        void* p;
        cudaGetSymbolAddress(&p, g_q);  qp  = (float*)p;
        cudaGetSymbolAddress(&p, g_kv); kvp = (float*)p;
        cudaGetSymbolAddress(&p, g_o);  op  = (float*)p;
        cudaFuncSetAttribute(attn_kernel, cudaFuncAttributeMaxDynamicSharedMemorySize,
                             ATT_SMEM_BYTES);
        cudaFuncSetAttribute(gemm_bf16x3, cudaFuncAttributeMaxDynamicSharedMemorySize,
                             GEMM_SMEM_BYTES);
        inited = true;
    }

    const dim3 blk(256);

    // 1) q = inputs_q @ Wq          [2048,1024] x [1024,1024]
    gemm_bf16x3<<<dim3(DMODEL / 128, (Bq * QLEN) / 128), blk, GEMM_SMEM_BYTES>>>(
        inputs_q, Wq, nullptr, qp, Bq * QLEN, NH * DHEAD, DMODEL);

    // 2) kv = inputs_kv @ Wkv       [16384,1024] x [1024,2048]
    gemm_bf16x3<<<dim3((NH * 2 * DHEAD) / 128, (Bq * KLEN) / 128), blk, GEMM_SMEM_BYTES>>>(
        inputs_kv, Wkv, nullptr, kvp, Bq * KLEN, NH * 2 * DHEAD, DMODEL);

    // 3) flash attention -> o
    attn_kernel<<<dim3(QLEN / 64, NH, Bq), blk, ATT_SMEM_BYTES>>>(qp, kvp, op);

    // 4) out = o @ Wproj + b        [2048,1024] x [1024,1024]
    gemm_bf16x3<<<dim3(DMODEL / 128, (Bq * QLEN) / 128), blk, GEMM_SMEM_BYTES>>>(
        op, Wproj, bproj, out, Bq * QLEN, DMODEL, NH * DHEAD);
}

// round 15
// speedup vs baseline: 1.2714x; 1.0008x over previous
#include <cuda_runtime.h>
#include <cuda_bf16.h>
#include <math.h>

// Problem constants
#define Bq      4
#define QLEN    512
#define KLEN    4096
#define DMODEL  1024
#define NH      8
#define DHEAD   128

// ---------------------------------------------------------------------------
// Scratch (device globals — allocation-free rule)
// ---------------------------------------------------------------------------
__device__ float g_q [(size_t)Bq * QLEN * NH * DHEAD];          // 8 MB
__device__ float g_kv[(size_t)Bq * KLEN * NH * 2 * DHEAD];      // 128 MB
__device__ float g_o [(size_t)Bq * QLEN * NH * DHEAD];          // 8 MB

// ===========================================================================
// bf16x3 tensor-core GEMM: C[M,N] = A[M,K] * B[K,N] (+bias), fp32 in/out.
// Split each fp32 into bf16 hi+lo; accumulate AhBh + AhBl + AlBh in fp32 via
// mma.sync.m16n8k16 -> ~16-bit effective mantissa (rel err ~1e-5).
// Block tile 128x128, BK=32, 256 threads (8 warps as 2(m) x 4(n), warp tile
// 64x32), double-buffered smem, register gmem prefetch.
// Requires M%128==0, N%128==0, K%32==0.
// ===========================================================================
#define A_PITCH 40    // bf16 elems per A smem row (conflict-free frag loads)
#define B_PITCH 136   // bf16 elems per B smem row
#define GEMM_A_ELTS (128 * A_PITCH)          // 5120
#define GEMM_B_ELTS (32 * B_PITCH)           // 4352
#define GEMM_BUF_ELTS (2 * GEMM_A_ELTS + 2 * GEMM_B_ELTS)   // 18944
#define GEMM_SMEM_BYTES (2 * GEMM_BUF_ELTS * 2)             // 75776

__device__ __forceinline__ unsigned pk16(__nv_bfloat16 lo, __nv_bfloat16 hi) {
    return (unsigned)__bfloat16_as_ushort(lo) |
           ((unsigned)__bfloat16_as_ushort(hi) << 16);
}
__device__ __forceinline__ void split_bf16(float x, __nv_bfloat16& h, __nv_bfloat16& l) {
    h = __float2bfloat16(x);
    l = __float2bfloat16(x - __bfloat162float(h));
}
__device__ __forceinline__ void mma16816(float* c, const unsigned* a, const unsigned* b) {
    asm volatile(
        "mma.sync.aligned.m16n8k16.row.col.f32.bf16.bf16.f32 "
        "{%0,%1,%2,%3}, {%4,%5,%6,%7}, {%8,%9}, {%0,%1,%2,%3};\n"
        : "+f"(c[0]), "+f"(c[1]), "+f"(c[2]), "+f"(c[3])
        : "r"(a[0]), "r"(a[1]), "r"(a[2]), "r"(a[3]), "r"(b[0]), "r"(b[1]));
}

__global__ __launch_bounds__(256, 1) void gemm_bf16x3(
    const float* __restrict__ A, const float* __restrict__ B,
    const float* __restrict__ bias, float* __restrict__ C,
    int M, int N, int K)
{
    extern __shared__ __nv_bfloat16 smg[];

    const int tid  = threadIdx.x;
    const int lane = tid & 31;
    const int wid  = tid >> 5;
    const int wm   = wid & 1;      // 0..1 : warp row (64 rows each)
    const int wn   = wid >> 1;     // 0..3 : warp col (32 cols each)
    const int m0   = blockIdx.y * 128;
    const int n0   = blockIdx.x * 128;

    // gmem load mapping (per thread: 4 float4 of A, 4 float4 of B per BK step)
    const int a_r = tid >> 3;              // 0..31 (row group, +it*32)
    const int a_c = (tid & 7) * 4;         // k col 0..28
    const int b_r = tid >> 5;              // 0..7  (k row, +it*8)
    const int b_c = (tid & 31) * 4;        // n col 0..124

    const float* Ag = A + (size_t)(m0 + a_r) * K + a_c;
    const float* Bg = B + (size_t)b_r * N + n0 + b_c;

    float4 apre[4], bpre[4];
#pragma unroll
    for (int it = 0; it < 4; it++) {
        apre[it] = *(const float4*)(Ag + (size_t)(it * 32) * K);
        bpre[it] = *(const float4*)(Bg + (size_t)(it * 8) * N);
    }

    float acc[4][4][4];
#pragma unroll
    for (int mt = 0; mt < 4; mt++)
#pragma unroll
        for (int nt = 0; nt < 4; nt++)
#pragma unroll
            for (int i = 0; i < 4; i++) acc[mt][nt][i] = 0.f;

    const int nk = K / 32;
    int buf = 0;
    for (int kt = 0; kt < nk; kt++) {
        __nv_bfloat16* Ah = smg + buf * GEMM_BUF_ELTS;
        __nv_bfloat16* Al = Ah + GEMM_A_ELTS;
        __nv_bfloat16* Bh = Ah + 2 * GEMM_A_ELTS;
        __nv_bfloat16* Bl = Bh + GEMM_B_ELTS;

        // ---- split + store current tiles to smem ----
#pragma unroll
        for (int it = 0; it < 4; it++) {
            {
                float4 v = apre[it];
                __nv_bfloat16 h0, h1, h2, h3, l0, l1, l2, l3;
                split_bf16(v.x, h0, l0); split_bf16(v.y, h1, l1);
                split_bf16(v.z, h2, l2); split_bf16(v.w, h3, l3);
                const int off = (a_r + it * 32) * A_PITCH + a_c;
                uint2 uh; uh.x = pk16(h0, h1); uh.y = pk16(h2, h3);
                uint2 ul; ul.x = pk16(l0, l1); ul.y = pk16(l2, l3);
                *(uint2*)&Ah[off] = uh;
                *(uint2*)&Al[off] = ul;
            }
            {
                float4 v = bpre[it];
                __nv_bfloat16 h0, h1, h2, h3, l0, l1, l2, l3;
                split_bf16(v.x, h0, l0); split_bf16(v.y, h1, l1);
                split_bf16(v.z, h2, l2); split_bf16(v.w, h3, l3);
                const int off = (b_r + it * 8) * B_PITCH + b_c;
                uint2 uh; uh.x = pk16(h0, h1); uh.y = pk16(h2, h3);
                uint2 ul; ul.x = pk16(l0, l1); ul.y = pk16(l2, l3);
                *(uint2*)&Bh[off] = uh;
                *(uint2*)&Bl[off] = ul;
            }
        }
        __syncthreads();

        // ---- prefetch next tiles to registers ----
        if (kt + 1 < nk) {
            const int knext = (kt + 1) * 32;
#pragma unroll
            for (int it = 0; it < 4; it++) {
                apre[it] = *(const float4*)(Ag + (size_t)(it * 32) * K + knext);
                bpre[it] = *(const float4*)(Bg + (size_t)(knext + it * 8) * N);
            }
        }

        // ---- compute: two k16 halves ----
#pragma unroll
        for (int h16 = 0; h16 < 2; h16++) {
            const int kb = h16 * 16;
            unsigned ah[4][4], al[4][4];
#pragma unroll
            for (int mt = 0; mt < 4; mt++) {
                const int r0 = wm * 64 + mt * 16 + (lane >> 2);
                const int cc = kb + (lane & 3) * 2;
                ah[mt][0] = *(const unsigned*)&Ah[r0 * A_PITCH + cc];
                ah[mt][1] = *(const unsigned*)&Ah[(r0 + 8) * A_PITCH + cc];
                ah[mt][2] = *(const unsigned*)&Ah[r0 * A_PITCH + cc + 8];
                ah[mt][3] = *(const unsigned*)&Ah[(r0 + 8) * A_PITCH + cc + 8];
                al[mt][0] = *(const unsigned*)&Al[r0 * A_PITCH + cc];
                al[mt][1] = *(const unsigned*)&Al[(r0 + 8) * A_PITCH + cc];
                al[mt][2] = *(const unsigned*)&Al[r0 * A_PITCH + cc + 8];
                al[mt][3] = *(const unsigned*)&Al[(r0 + 8) * A_PITCH + cc + 8];
            }
            unsigned bh[4][2], bl[4][2];
#pragma unroll
            for (int nt = 0; nt < 4; nt++) {
                const int nc = wn * 32 + nt * 8 + (lane >> 2);
                const int k0 = kb + (lane & 3) * 2;
                bh[nt][0] = pk16(Bh[k0 * B_PITCH + nc],       Bh[(k0 + 1) * B_PITCH + nc]);
                bh[nt][1] = pk16(Bh[(k0 + 8) * B_PITCH + nc], Bh[(k0 + 9) * B_PITCH + nc]);
                bl[nt][0] = pk16(Bl[k0 * B_PITCH + nc],       Bl[(k0 + 1) * B_PITCH + nc]);
                bl[nt][1] = pk16(Bl[(k0 + 8) * B_PITCH + nc], Bl[(k0 + 9) * B_PITCH + nc]);
            }
#pragma unroll
            for (int mt = 0; mt < 4; mt++)
#pragma unroll
                for (int nt = 0; nt < 4; nt++) {
                    mma16816(acc[mt][nt], ah[mt], bh[nt]);
                    mma16816(acc[mt][nt], ah[mt], bl[nt]);
                    mma16816(acc[mt][nt], al[mt], bh[nt]);
                }
        }
        buf ^= 1;
    }

    // ---- epilogue ----
#pragma unroll
    for (int mt = 0; mt < 4; mt++) {
        const int gm = m0 + wm * 64 + mt * 16 + (lane >> 2);
#pragma unroll
        for (int nt = 0; nt < 4; nt++) {
            const int gn = n0 + wn * 32 + nt * 8 + (lane & 3) * 2;
            float2 v0 = make_float2(acc[mt][nt][0], acc[mt][nt][1]);
            float2 v1 = make_float2(acc[mt][nt][2], acc[mt][nt][3]);
            if (bias) {
                float2 bb = *(const float2*)&bias[gn];
                v0.x += bb.x; v0.y += bb.y;
                v1.x += bb.x; v1.y += bb.y;
            }
            *(float2*)&C[(size_t)gm * N + gn]       = v0;
            *(float2*)&C[(size_t)(gm + 8) * N + gn] = v1;
        }
    }
}

// ---------------------------------------------------------------------------
// Flash attention, fp32, 64 queries x 64 keys per tile, 256 threads.
// (unchanged from round 12 — next optimization target)
// ---------------------------------------------------------------------------
#define QT_STRIDE 68
#define ATT_SMEM_FLOATS (128 * QT_STRIDE * 2 + 64 * 128 + 64 * QT_STRIDE)
#define ATT_SMEM_BYTES  (ATT_SMEM_FLOATS * 4)

__device__ __forceinline__ void fma44(float4& a, float p, const float4& v) {
    a.x += p * v.x; a.y += p * v.y; a.z += p * v.z; a.w += p * v.w;
}
__device__ __forceinline__ void scale4(float4& a, float c) {
    a.x *= c; a.y *= c; a.z *= c; a.w *= c;
}

__device__ __forceinline__ void softmax_row(
    float4 s, float scale, float& m, float& l,
    float4& oa, float4& ob, float* Ps, int rowoff, int tx)
{
    float a0 = s.x * scale, a1 = s.y * scale, a2 = s.z * scale, a3 = s.w * scale;
    float rm = fmaxf(fmaxf(a0, a1), fmaxf(a2, a3));
#pragma unroll
    for (int msk = 1; msk < 16; msk <<= 1)
        rm = fmaxf(rm, __shfl_xor_sync(0xffffffffu, rm, msk));
    const float mn   = fmaxf(m, rm);
    const float corr = __expf(m - mn);
    m = mn;
    float p0 = __expf(a0 - mn), p1 = __expf(a1 - mn);
    float p2 = __expf(a2 - mn), p3 = __expf(a3 - mn);
    float rsum = p0 + p1 + p2 + p3;
#pragma unroll
    for (int msk = 1; msk < 16; msk <<= 1)
        rsum += __shfl_xor_sync(0xffffffffu, rsum, msk);
    l = l * corr + rsum;
    scale4(oa, corr);
    scale4(ob, corr);
    *(float4*)&Ps[rowoff + tx * 4] = make_float4(p0, p1, p2, p3);
}

__global__ __launch_bounds__(256, 1) void attn_kernel(
    const float* __restrict__ Qm, const float* __restrict__ KVm,
    float* __restrict__ Om)
{
    extern __shared__ float sm[];
    float* Qt = sm;                        // [128][68] kk-major, swizzled
    float* Kt = Qt + 128 * QT_STRIDE;      // [128][68]
    float* Vs = Kt + 128 * QT_STRIDE;      // [64][128] row-major
    float* Ps = Vs + 64 * 128;             // [64][68]

    const int tid = threadIdx.x;
    const int tx  = tid & 15;
    const int ty  = tid >> 4;
    const int q0  = blockIdx.x * 64;
    const int h   = blockIdx.y;
    const int b   = blockIdx.z;

    const float scale = 0.088388347648318447f;  // 1/sqrt(128)

    // ---- load Q tile (transposed + XOR swizzle) ----
    const float* Qbase = Qm + ((size_t)(b * QLEN + q0) * NH + h) * DHEAD;
#pragma unroll
    for (int it = 0; it < 8; it++) {
        const int idx = tid + it * 256;        // 0..2047
        const int r   = idx >> 5;              // query row 0..63
        const int c4  = (idx & 31) << 2;       // dh col, step 4
        float4 v = *(const float4*)(Qbase + (size_t)r * (NH * DHEAD) + c4);
        const int f  = c4 & 28;
        const int rs = r ^ f;
        Qt[(c4 + 0) * QT_STRIDE + rs] = v.x;
        Qt[(c4 + 1) * QT_STRIDE + rs] = v.y;
        Qt[(c4 + 2) * QT_STRIDE + rs] = v.z;
        Qt[(c4 + 3) * QT_STRIDE + rs] = v.w;
    }

    float  m_i[4], l_i[4];
    float4 oA[4], oB[4];
#pragma unroll
    for (int i = 0; i < 4; i++) {
        m_i[i] = -1e30f; l_i[i] = 0.f;
        oA[i] = make_float4(0.f, 0.f, 0.f, 0.f);
        oB[i] = make_float4(0.f, 0.f, 0.f, 0.f);
    }

    for (int kt = 0; kt < KLEN / 64; kt++) {
        __syncthreads();   // prior tile's smem reads done (also fences Q stores on kt==0)

        // ---- load K (transposed+swizzled) and V (row-major) tiles ----
        const int k0 = kt * 64;
        const float* Kbase = KVm + ((size_t)(b * KLEN + k0) * NH + h) * (2 * DHEAD);
#pragma unroll
        for (int it = 0; it < 8; it++) {
            const int idx = tid + it * 256;
            const int r   = idx >> 5;
            const int c4  = (idx & 31) << 2;
            const float* rowp = Kbase + (size_t)r * (NH * 2 * DHEAD);
            float4 kv4 = *(const float4*)(rowp + c4);
            const int f  = c4 & 28;
            const int rs = r ^ f;
            Kt[(c4 + 0) * QT_STRIDE + rs] = kv4.x;
            Kt[(c4 + 1) * QT_STRIDE + rs] = kv4.y;
            Kt[(c4 + 2) * QT_STRIDE + rs] = kv4.z;
            Kt[(c4 + 3) * QT_STRIDE + rs] = kv4.w;
            float4 v4 = *(const float4*)(rowp + DHEAD + c4);
            *(float4*)&Vs[r * 128 + c4] = v4;
        }
        __syncthreads();

        // ---- S = Q K^T  (rows ty*4.., cols tx*4..) ----
        float4 s0 = make_float4(0.f, 0.f, 0.f, 0.f);
        float4 s1 = s0, s2 = s0, s3 = s0;
#pragma unroll 8
        for (int kk = 0; kk < 128; kk++) {
            const int f = kk & 28;
            float4 a  = *(const float4*)&Qt[kk * QT_STRIDE + ((ty * 4) ^ f)];
            float4 bq = *(const float4*)&Kt[kk * QT_STRIDE + ((tx * 4) ^ f)];
            s0.x += a.x * bq.x; s0.y += a.x * bq.y; s0.z += a.x * bq.z; s0.w += a.x * bq.w;
            s1.x += a.y * bq.x; s1.y += a.y * bq.y; s1.z += a.y * bq.z; s1.w += a.y * bq.w;
            s2.x += a.z * bq.x; s2.y += a.z * bq.y; s2.z += a.z * bq.z; s2.w += a.z * bq.w;
            s3.x += a.w * bq.x; s3.y += a.w * bq.y; s3.z += a.w * bq.z; s3.w += a.w * bq.w;
        }

        // ---- online softmax update (per row), write P tile ----
        softmax_row(s0, scale, m_i[0], l_i[0], oA[0], oB[0], Ps, (ty * 4 + 0) * QT_STRIDE, tx);
        softmax_row(s1, scale, m_i[1], l_i[1], oA[1], oB[1], Ps, (ty * 4 + 1) * QT_STRIDE, tx);
        softmax_row(s2, scale, m_i[2], l_i[2], oA[2], oB[2], Ps, (ty * 4 + 2) * QT_STRIDE, tx);
        softmax_row(s3, scale, m_i[3], l_i[3], oA[3], oB[3], Ps, (ty * 4 + 3) * QT_STRIDE, tx);
        __syncthreads();

        // ---- O += P * V  (rows ty*4.., dh cols tx*8..) ----
#pragma unroll 2
        for (int j4 = 0; j4 < 16; j4++) {
            const int pb = j4 * 4;
            float4 pr0 = *(const float4*)&Ps[(ty * 4 + 0) * QT_STRIDE + pb];
            float4 pr1 = *(const float4*)&Ps[(ty * 4 + 1) * QT_STRIDE + pb];
            float4 pr2 = *(const float4*)&Ps[(ty * 4 + 2) * QT_STRIDE + pb];
            float4 pr3 = *(const float4*)&Ps[(ty * 4 + 3) * QT_STRIDE + pb];
#pragma unroll
            for (int jj = 0; jj < 4; jj++) {
                const float p0 = (jj == 0) ? pr0.x : (jj == 1) ? pr0.y : (jj == 2) ? pr0.z : pr0.w;
                const float p1 = (jj == 0) ? pr1.x : (jj == 1) ? pr1.y : (jj == 2) ? pr1.z : pr1.w;
                const float p2 = (jj == 0) ? pr2.x : (jj == 1) ? pr2.y : (jj == 2) ? pr2.z : pr2.w;
                const float p3 = (jj == 0) ? pr3.x : (jj == 1) ? pr3.y : (jj == 2) ? pr3.z : pr3.w;
                float4 v0 = *(const float4*)&Vs[(pb + jj) * 128 + tx * 8];
                float4 v1 = *(const float4*)&Vs[(pb + jj) * 128 + tx * 8 + 4];
                fma44(oA[0], p0, v0); fma44(oB[0], p0, v1);
                fma44(oA[1], p1, v0); fma44(oB[1], p1, v1);
                fma44(oA[2], p2, v0); fma44(oB[2], p2, v1);
                fma44(oA[3], p3, v0); fma44(oB[3], p3, v1);
            }
        }
    }

    // ---- epilogue: normalize and store ----
    float* Obase = Om + ((size_t)(b * QLEN + q0) * NH + h) * DHEAD;
#pragma unroll
    for (int i = 0; i < 4; i++) {
        const int r = ty * 4 + i;
        const float inv = 1.f / l_i[i];
        float4 v0 = oA[i], v1 = oB[i];
        scale4(v0, inv);
        scale4(v1, inv);
        *(float4*)&Obase[(size_t)r * (NH * DHEAD) + tx * 8]     = v0;
        *(float4*)&Obase[(size_t)r * (NH * DHEAD) + tx * 8 + 4] = v1;
    }
}

// ---------------------------------------------------------------------------
// Launch
// ---------------------------------------------------------------------------
extern "C" void kernel_launch(void* const* d_in, const int* in_sizes, int n_in,
                              void* d_out, int out_size)
{
    (void)in_sizes; (void)n_in; (void)out_size;

    const float* inputs_q  = (const float*)d_in[0];
    const float* inputs_kv = (const float*)d_in[1];
    const float* Wq        = (const float*)d_in[2];
    const float* Wkv       = (const float*)d_in[3];
    const float* Wproj     = (const float*)d_in[4];
    const float* bproj     = (const float*)d_in[5];
    float* out = (float*)d_out;

    // One-time setup (first call is the uncaptured correctness run).
    static float* qp  = nullptr;
    static float* kvp = nullptr;
    static float* op  = nullptr;
    static bool inited = false;
    if (!inited) {
        void* p;
        cudaGetSymbolAddress(&p, g_q);  qp  = (float*)p;
        cudaGetSymbolAddress(&p, g_kv); kvp = (float*)p;
        cudaGetSymbolAddress(&p, g_o);  op  = (float*)p;
        cudaFuncSetAttribute(attn_kernel, cudaFuncAttributeMaxDynamicSharedMemorySize,
                             ATT_SMEM_BYTES);
        cudaFuncSetAttribute(gemm_bf16x3, cudaFuncAttributeMaxDynamicSharedMemorySize,
                             GEMM_SMEM_BYTES);
        inited = true;
    }

    const dim3 blk(256);

    // 1) q = inputs_q @ Wq          [2048,1024] x [1024,1024]
    gemm_bf16x3<<<dim3(DMODEL / 128, (Bq * QLEN) / 128), blk, GEMM_SMEM_BYTES>>>(
        inputs_q, Wq, nullptr, qp, Bq * QLEN, NH * DHEAD, DMODEL);

    // 2) kv = inputs_kv @ Wkv       [16384,1024] x [1024,2048]
    gemm_bf16x3<<<dim3((NH * 2 * DHEAD) / 128, (Bq * KLEN) / 128), blk, GEMM_SMEM_BYTES>>>(
        inputs_kv, Wkv, nullptr, kvp, Bq * KLEN, NH * 2 * DHEAD, DMODEL);

    // 3) flash attention -> o
    attn_kernel<<<dim3(QLEN / 64, NH, Bq), blk, ATT_SMEM_BYTES>>>(qp, kvp, op);

    // 4) out = o @ Wproj + b        [2048,1024] x [1024,1024]
    gemm_bf16x3<<<dim3(DMODEL / 128, (Bq * QLEN) / 128), blk, GEMM_SMEM_BYTES>>>(
        op, Wproj, bproj, out, Bq * QLEN, DMODEL, NH * DHEAD);
}

// round 16
// speedup vs baseline: 1.2719x; 1.0004x over previous
#include <cuda_runtime.h>
#include <cuda_bf16.h>
#include <math.h>

// Problem constants
#define Bq      4
#define QLEN    512
#define KLEN    4096
#define DMODEL  1024
#define NH      8
#define DHEAD   128

// ---------------------------------------------------------------------------
// Scratch (device globals — allocation-free rule)
// ---------------------------------------------------------------------------
__device__ float g_q [(size_t)Bq * QLEN * NH * DHEAD];          // 8 MB
__device__ float g_kv[(size_t)Bq * KLEN * NH * 2 * DHEAD];      // 128 MB
__device__ float g_o [(size_t)Bq * QLEN * NH * DHEAD];          // 8 MB

// ===========================================================================
// bf16x3 tensor-core GEMM: C[M,N] = A[M,K] * B[K,N] (+bias), fp32 in/out.
// Split each fp32 into bf16 hi+lo; accumulate AhBh + AhBl + AlBh in fp32 via
// mma.sync.m16n8k16 -> ~16-bit effective mantissa (rel err ~1e-5).
// Block tile 128x128, BK=32, 256 threads (8 warps as 2(m) x 4(n), warp tile
// 64x32), double-buffered smem, register gmem prefetch.
// Requires M%128==0, N%128==0, K%32==0.
// ===========================================================================
#define A_PITCH 40    // bf16 elems per A smem row (conflict-free frag loads)
#define B_PITCH 136   // bf16 elems per B smem row
#define GEMM_A_ELTS (128 * A_PITCH)          // 5120
#define GEMM_B_ELTS (32 * B_PITCH)           // 4352
#define GEMM_BUF_ELTS (2 * GEMM_A_ELTS + 2 * GEMM_B_ELTS)   // 18944
#define GEMM_SMEM_BYTES (2 * GEMM_BUF_ELTS * 2)             // 75776

__device__ __forceinline__ unsigned pk16(__nv_bfloat16 lo, __nv_bfloat16 hi) {
    return (unsigned)__bfloat16_as_ushort(lo) |
           ((unsigned)__bfloat16_as_ushort(hi) << 16);
}
__device__ __forceinline__ void split_bf16(float x, __nv_bfloat16& h, __nv_bfloat16& l) {
    h = __float2bfloat16(x);
    l = __float2bfloat16(x - __bfloat162float(h));
}
__device__ __forceinline__ void mma16816(float* c, const unsigned* a, const unsigned* b) {
    asm volatile(
        "mma.sync.aligned.m16n8k16.row.col.f32.bf16.bf16.f32 "
        "{%0,%1,%2,%3}, {%4,%5,%6,%7}, {%8,%9}, {%0,%1,%2,%3};\n"
        : "+f"(c[0]), "+f"(c[1]), "+f"(c[2]), "+f"(c[3])
        : "r"(a[0]), "r"(a[1]), "r"(a[2]), "r"(a[3]), "r"(b[0]), "r"(b[1]));
}

__global__ __launch_bounds__(256, 1) void gemm_bf16x3(
    const float* __restrict__ A, const float* __restrict__ B,
    const float* __restrict__ bias, float* __restrict__ C,
    int M, int N, int K)
{
    extern __shared__ __nv_bfloat16 smg[];

    const int tid  = threadIdx.x;
    const int lane = tid & 31;
    const int wid  = tid >> 5;
    const int wm   = wid & 1;      // 0..1 : warp row (64 rows each)
    const int wn   = wid >> 1;     // 0..3 : warp col (32 cols each)
    const int m0   = blockIdx.y * 128;
    const int n0   = blockIdx.x * 128;

    // gmem load mapping (per thread: 4 float4 of A, 4 float4 of B per BK step)
    const int a_r = tid >> 3;              // 0..31 (row group, +it*32)
    const int a_c = (tid & 7) * 4;         // k col 0..28
    const int b_r = tid >> 5;              // 0..7  (k row, +it*8)
    const int b_c = (tid & 31) * 4;        // n col 0..124

    const float* Ag = A + (size_t)(m0 + a_r) * K + a_c;
    const float* Bg = B + (size_t)b_r * N + n0 + b_c;

    float4 apre[4], bpre[4];
#pragma unroll
    for (int it = 0; it < 4; it++) {
        apre[it] = *(const float4*)(Ag + (size_t)(it * 32) * K);
        bpre[it] = *(const float4*)(Bg + (size_t)(it * 8) * N);
    }

    float acc[4][4][4];
#pragma unroll
    for (int mt = 0; mt < 4; mt++)
#pragma unroll
        for (int nt = 0; nt < 4; nt++)
#pragma unroll
            for (int i = 0; i < 4; i++) acc[mt][nt][i] = 0.f;

    const int nk = K / 32;
    int buf = 0;
    for (int kt = 0; kt < nk; kt++) {
        __nv_bfloat16* Ah = smg + buf * GEMM_BUF_ELTS;
        __nv_bfloat16* Al = Ah + GEMM_A_ELTS;
        __nv_bfloat16* Bh = Ah + 2 * GEMM_A_ELTS;
        __nv_bfloat16* Bl = Bh + GEMM_B_ELTS;

        // ---- split + store current tiles to smem ----
#pragma unroll
        for (int it = 0; it < 4; it++) {
            {
                float4 v = apre[it];
                __nv_bfloat16 h0, h1, h2, h3, l0, l1, l2, l3;
                split_bf16(v.x, h0, l0); split_bf16(v.y, h1, l1);
                split_bf16(v.z, h2, l2); split_bf16(v.w, h3, l3);
                const int off = (a_r + it * 32) * A_PITCH + a_c;
                uint2 uh; uh.x = pk16(h0, h1); uh.y = pk16(h2, h3);
                uint2 ul; ul.x = pk16(l0, l1); ul.y = pk16(l2, l3);
                *(uint2*)&Ah[off] = uh;
                *(uint2*)&Al[off] = ul;
            }
            {
                float4 v = bpre[it];
                __nv_bfloat16 h0, h1, h2, h3, l0, l1, l2, l3;
                split_bf16(v.x, h0, l0); split_bf16(v.y, h1, l1);
                split_bf16(v.z, h2, l2); split_bf16(v.w, h3, l3);
                const int off = (b_r + it * 8) * B_PITCH + b_c;
                uint2 uh; uh.x = pk16(h0, h1); uh.y = pk16(h2, h3);
                uint2 ul; ul.x = pk16(l0, l1); ul.y = pk16(l2, l3);
                *(uint2*)&Bh[off] = uh;
                *(uint2*)&Bl[off] = ul;
            }
        }
        __syncthreads();

        // ---- prefetch next tiles to registers ----
        if (kt + 1 < nk) {
            const int knext = (kt + 1) * 32;
#pragma unroll
            for (int it = 0; it < 4; it++) {
                apre[it] = *(const float4*)(Ag + (size_t)(it * 32) * K + knext);
                bpre[it] = *(const float4*)(Bg + (size_t)(knext + it * 8) * N);
            }
        }

        // ---- compute: two k16 halves ----
#pragma unroll
        for (int h16 = 0; h16 < 2; h16++) {
            const int kb = h16 * 16;
            unsigned ah[4][4], al[4][4];
#pragma unroll
            for (int mt = 0; mt < 4; mt++) {
                const int r0 = wm * 64 + mt * 16 + (lane >> 2);
                const int cc = kb + (lane & 3) * 2;
                ah[mt][0] = *(const unsigned*)&Ah[r0 * A_PITCH + cc];
                ah[mt][1] = *(const unsigned*)&Ah[(r0 + 8) * A_PITCH + cc];
                ah[mt][2] = *(const unsigned*)&Ah[r0 * A_PITCH + cc + 8];
                ah[mt][3] = *(const unsigned*)&Ah[(r0 + 8) * A_PITCH + cc + 8];
                al[mt][0] = *(const unsigned*)&Al[r0 * A_PITCH + cc];
                al[mt][1] = *(const unsigned*)&Al[(r0 + 8) * A_PITCH + cc];
                al[mt][2] = *(const unsigned*)&Al[r0 * A_PITCH + cc + 8];
                al[mt][3] = *(const unsigned*)&Al[(r0 + 8) * A_PITCH + cc + 8];
            }
            unsigned bh[4][2], bl[4][2];
#pragma unroll
            for (int nt = 0; nt < 4; nt++) {
                const int nc = wn * 32 + nt * 8 + (lane >> 2);
                const int k0 = kb + (lane & 3) * 2;
                bh[nt][0] = pk16(Bh[k0 * B_PITCH + nc],       Bh[(k0 + 1) * B_PITCH + nc]);
                bh[nt][1] = pk16(Bh[(k0 + 8) * B_PITCH + nc], Bh[(k0 + 9) * B_PITCH + nc]);
                bl[nt][0] = pk16(Bl[k0 * B_PITCH + nc],       Bl[(k0 + 1) * B_PITCH + nc]);
                bl[nt][1] = pk16(Bl[(k0 + 8) * B_PITCH + nc], Bl[(k0 + 9) * B_PITCH + nc]);
            }
#pragma unroll
            for (int mt = 0; mt < 4; mt++)
#pragma unroll
                for (int nt = 0; nt < 4; nt++) {
                    mma16816(acc[mt][nt], ah[mt], bh[nt]);
                    mma16816(acc[mt][nt], ah[mt], bl[nt]);
                    mma16816(acc[mt][nt], al[mt], bh[nt]);
                }
        }
        buf ^= 1;
    }

    // ---- epilogue ----
#pragma unroll
    for (int mt = 0; mt < 4; mt++) {
        const int gm = m0 + wm * 64 + mt * 16 + (lane >> 2);
#pragma unroll
        for (int nt = 0; nt < 4; nt++) {
            const int gn = n0 + wn * 32 + nt * 8 + (lane & 3) * 2;
            float2 v0 = make_float2(acc[mt][nt][0], acc[mt][nt][1]);
            float2 v1 = make_float2(acc[mt][nt][2], acc[mt][nt][3]);
            if (bias) {
                float2 bb = *(const float2*)&bias[gn];
                v0.x += bb.x; v0.y += bb.y;
                v1.x += bb.x; v1.y += bb.y;
            }
            *(float2*)&C[(size_t)gm * N + gn]       = v0;
            *(float2*)&C[(size_t)(gm + 8) * N + gn] = v1;
        }
    }
}

// ---------------------------------------------------------------------------
// Flash attention, fp32, 64 queries x 64 keys per tile, 256 threads.
// (unchanged from round 12 — next optimization target)
// ---------------------------------------------------------------------------
#define QT_STRIDE 68
#define ATT_SMEM_FLOATS (128 * QT_STRIDE * 2 + 64 * 128 + 64 * QT_STRIDE)
#define ATT_SMEM_BYTES  (ATT_SMEM_FLOATS * 4)

__device__ __forceinline__ void fma44(float4& a, float p, const float4& v) {
    a.x += p * v.x; a.y += p * v.y; a.z += p * v.z; a.w += p * v.w;
}
__device__ __forceinline__ void scale4(float4& a, float c) {
    a.x *= c; a.y *= c; a.z *= c; a.w *= c;
}

__device__ __forceinline__ void softmax_row(
    float4 s, float scale, float& m, float& l,
    float4& oa, float4& ob, float* Ps, int rowoff, int tx)
{
    float a0 = s.x * scale, a1 = s.y * scale, a2 = s.z * scale, a3 = s.w * scale;
    float rm = fmaxf(fmaxf(a0, a1), fmaxf(a2, a3));
#pragma unroll
    for (int msk = 1; msk < 16; msk <<= 1)
        rm = fmaxf(rm, __shfl_xor_sync(0xffffffffu, rm, msk));
    const float mn   = fmaxf(m, rm);
    const float corr = __expf(m - mn);
    m = mn;
    float p0 = __expf(a0 - mn), p1 = __expf(a1 - mn);
    float p2 = __expf(a2 - mn), p3 = __expf(a3 - mn);
    float rsum = p0 + p1 + p2 + p3;
#pragma unroll
    for (int msk = 1; msk < 16; msk <<= 1)
        rsum += __shfl_xor_sync(0xffffffffu, rsum, msk);
    l = l * corr + rsum;
    scale4(oa, corr);
    scale4(ob, corr);
    *(float4*)&Ps[rowoff + tx * 4] = make_float4(p0, p1, p2, p3);
}

__global__ __launch_bounds__(256, 1) void attn_kernel(
    const float* __restrict__ Qm, const float* __restrict__ KVm,
    float* __restrict__ Om)
{
    extern __shared__ float sm[];
    float* Qt = sm;                        // [128][68] kk-major, swizzled
    float* Kt = Qt + 128 * QT_STRIDE;      // [128][68]
    float* Vs = Kt + 128 * QT_STRIDE;      // [64][128] row-major
    float* Ps = Vs + 64 * 128;             // [64][68]

    const int tid = threadIdx.x;
    const int tx  = tid & 15;
    const int ty  = tid >> 4;
    const int q0  = blockIdx.x * 64;
    const int h   = blockIdx.y;
    const int b   = blockIdx.z;

    const float scale = 0.088388347648318447f;  // 1/sqrt(128)

    // ---- load Q tile (transposed + XOR swizzle) ----
    const float* Qbase = Qm + ((size_t)(b * QLEN + q0) * NH + h) * DHEAD;
#pragma unroll
    for (int it = 0; it < 8; it++) {
        const int idx = tid + it * 256;        // 0..2047
        const int r   = idx >> 5;              // query row 0..63
        const int c4  = (idx & 31) << 2;       // dh col, step 4
        float4 v = *(const float4*)(Qbase + (size_t)r * (NH * DHEAD) + c4);
        const int f  = c4 & 28;
        const int rs = r ^ f;
        Qt[(c4 + 0) * QT_STRIDE + rs] = v.x;
        Qt[(c4 + 1) * QT_STRIDE + rs] = v.y;
        Qt[(c4 + 2) * QT_STRIDE + rs] = v.z;
        Qt[(c4 + 3) * QT_STRIDE + rs] = v.w;
    }

    float  m_i[4], l_i[4];
    float4 oA[4], oB[4];
#pragma unroll
    for (int i = 0; i < 4; i++) {
        m_i[i] = -1e30f; l_i[i] = 0.f;
        oA[i] = make_float4(0.f, 0.f, 0.f, 0.f);
        oB[i] = make_float4(0.f, 0.f, 0.f, 0.f);
    }

    for (int kt = 0; kt < KLEN / 64; kt++) {
        __syncthreads();   // prior tile's smem reads done (also fences Q stores on kt==0)

        // ---- load K (transposed+swizzled) and V (row-major) tiles ----
        const int k0 = kt * 64;
        const float* Kbase = KVm + ((size_t)(b * KLEN + k0) * NH + h) * (2 * DHEAD);
#pragma unroll
        for (int it = 0; it < 8; it++) {
            const int idx = tid + it * 256;
            const int r   = idx >> 5;
            const int c4  = (idx & 31) << 2;
            const float* rowp = Kbase + (size_t)r * (NH * 2 * DHEAD);
            float4 kv4 = *(const float4*)(rowp + c4);
            const int f  = c4 & 28;
            const int rs = r ^ f;
            Kt[(c4 + 0) * QT_STRIDE + rs] = kv4.x;
            Kt[(c4 + 1) * QT_STRIDE + rs] = kv4.y;
            Kt[(c4 + 2) * QT_STRIDE + rs] = kv4.z;
            Kt[(c4 + 3) * QT_STRIDE + rs] = kv4.w;
            float4 v4 = *(const float4*)(rowp + DHEAD + c4);
            *(float4*)&Vs[r * 128 + c4] = v4;
        }
        __syncthreads();

        // ---- S = Q K^T  (rows ty*4.., cols tx*4..) ----
        float4 s0 = make_float4(0.f, 0.f, 0.f, 0.f);
        float4 s1 = s0, s2 = s0, s3 = s0;
#pragma unroll 8
        for (int kk = 0; kk < 128; kk++) {
            const int f = kk & 28;
            float4 a  = *(const float4*)&Qt[kk * QT_STRIDE + ((ty * 4) ^ f)];
            float4 bq = *(const float4*)&Kt[kk * QT_STRIDE + ((tx * 4) ^ f)];
            s0.x += a.x * bq.x; s0.y += a.x * bq.y; s0.z += a.x * bq.z; s0.w += a.x * bq.w;
            s1.x += a.y * bq.x; s1.y += a.y * bq.y; s1.z += a.y * bq.z; s1.w += a.y * bq.w;
            s2.x += a.z * bq.x; s2.y += a.z * bq.y; s2.z += a.z * bq.z; s2.w += a.z * bq.w;
            s3.x += a.w * bq.x; s3.y += a.w * bq.y; s3.z += a.w * bq.z; s3.w += a.w * bq.w;
        }

        // ---- online softmax update (per row), write P tile ----
        softmax_row(s0, scale, m_i[0], l_i[0], oA[0], oB[0], Ps, (ty * 4 + 0) * QT_STRIDE, tx);
        softmax_row(s1, scale, m_i[1], l_i[1], oA[1], oB[1], Ps, (ty * 4 + 1) * QT_STRIDE, tx);
        softmax_row(s2, scale, m_i[2], l_i[2], oA[2], oB[2], Ps, (ty * 4 + 2) * QT_STRIDE, tx);
        softmax_row(s3, scale, m_i[3], l_i[3], oA[3], oB[3], Ps, (ty * 4 + 3) * QT_STRIDE, tx);
        __syncthreads();

        // ---- O += P * V  (rows ty*4.., dh cols tx*8..) ----
#pragma unroll 2
        for (int j4 = 0; j4 < 16; j4++) {
            const int pb = j4 * 4;
            float4 pr0 = *(const float4*)&Ps[(ty * 4 + 0) * QT_STRIDE + pb];
            float4 pr1 = *(const float4*)&Ps[(ty * 4 + 1) * QT_STRIDE + pb];
            float4 pr2 = *(const float4*)&Ps[(ty * 4 + 2) * QT_STRIDE + pb];
            float4 pr3 = *(const float4*)&Ps[(ty * 4 + 3) * QT_STRIDE + pb];
#pragma unroll
            for (int jj = 0; jj < 4; jj++) {
                const float p0 = (jj == 0) ? pr0.x : (jj == 1) ? pr0.y : (jj == 2) ? pr0.z : pr0.w;
                const float p1 = (jj == 0) ? pr1.x : (jj == 1) ? pr1.y : (jj == 2) ? pr1.z : pr1.w;
                const float p2 = (jj == 0) ? pr2.x : (jj == 1) ? pr2.y : (jj == 2) ? pr2.z : pr2.w;
                const float p3 = (jj == 0) ? pr3.x : (jj == 1) ? pr3.y : (jj == 2) ? pr3.z : pr3.w;
                float4 v0 = *(const float4*)&Vs[(pb + jj) * 128 + tx * 8];
                float4 v1 = *(const float4*)&Vs[(pb + jj) * 128 + tx * 8 + 4];
                fma44(oA[0], p0, v0); fma44(oB[0], p0, v1);
                fma44(oA[1], p1, v0); fma44(oB[1], p1, v1);
                fma44(oA[2], p2, v0); fma44(oB[2], p2, v1);
                fma44(oA[3], p3, v0); fma44(oB[3], p3, v1);
            }
        }
    }

    // ---- epilogue: normalize and store ----
    float* Obase = Om + ((size_t)(b * QLEN + q0) * NH + h) * DHEAD;
#pragma unroll
    for (int i = 0; i < 4; i++) {
        const int r = ty * 4 + i;
        const float inv = 1.f / l_i[i];
        float4 v0 = oA[i], v1 = oB[i];
        scale4(v0, inv);
        scale4(v1, inv);
        *(float4*)&Obase[(size_t)r * (NH * DHEAD) + tx * 8]     = v0;
        *(float4*)&Obase[(size_t)r * (NH * DHEAD) + tx * 8 + 4] = v1;
    }
}

// ---------------------------------------------------------------------------
// Launch
// ---------------------------------------------------------------------------
extern "C" void kernel_launch(void* const* d_in, const int* in_sizes, int n_in,
                              void* d_out, int out_size)
{
    (void)in_sizes; (void)n_in; (void)out_size;

    const float* inputs_q  = (const float*)d_in[0];
    const float* inputs_kv = (const float*)d_in[1];
    const float* Wq        = (const float*)d_in[2];
    const float* Wkv       = (const float*)d_in[3];
    const float* Wproj     = (const float*)d_in[4];
    const float* bproj     = (const float*)d_in[5];
    float* out = (float*)d_out;

    // One-time setup (first call is the uncaptured correctness run).
    static float* qp  = nullptr;
    static float* kvp = nullptr;
    static float* op  = nullptr;
    static bool inited = false;
    if (!inited) {
        void* p;
        cudaGetSymbolAddress(&p, g_q);  qp  = (float*)p;
        cudaGetSymbolAddress(&p, g_kv); kvp = (float*)p;
        cudaGetSymbolAddress(&p, g_o);  op  = (float*)p;
        cudaFuncSetAttribute(attn_kernel, cudaFuncAttributeMaxDynamicSharedMemorySize,
                             ATT_SMEM_BYTES);
        cudaFuncSetAttribute(gemm_bf16x3, cudaFuncAttributeMaxDynamicSharedMemorySize,
                             GEMM_SMEM_BYTES);
        inited = true;
    }

    const dim3 blk(256);

    // 1) q = inputs_q @ Wq          [2048,1024] x [1024,1024]
    gemm_bf16x3<<<dim3(DMODEL / 128, (Bq * QLEN) / 128), blk, GEMM_SMEM_BYTES>>>(
        inputs_q, Wq, nullptr, qp, Bq * QLEN, NH * DHEAD, DMODEL);

    // 2) kv = inputs_kv @ Wkv       [16384,1024] x [1024,2048]
    gemm_bf16x3<<<dim3((NH * 2 * DHEAD) / 128, (Bq * KLEN) / 128), blk, GEMM_SMEM_BYTES>>>(
        inputs_kv, Wkv, nullptr, kvp, Bq * KLEN, NH * 2 * DHEAD, DMODEL);

    // 3) flash attention -> o
    attn_kernel<<<dim3(QLEN / 64, NH, Bq), blk, ATT_SMEM_BYTES>>>(qp, kvp, op);

    // 4) out = o @ Wproj + b        [2048,1024] x [1024,1024]
    gemm_bf16x3<<<dim3(DMODEL / 128, (Bq * QLEN) / 128), blk, GEMM_SMEM_BYTES>>>(
        op, Wproj, bproj, out, Bq * QLEN, DMODEL, NH * DHEAD);
}